// round 1
// baseline (speedup 1.0000x reference)
#include <cuda_runtime.h>
#include <cstdint>

// ---------------------------------------------------------------------------
// MultiViewTripletLoss: fused normalize + (A·Aᵀ, A·P0ᵀ, A·P1ᵀ) masked row-max
// + loss reduction.  dist(x,y) = sqrt(2 - 2 x·y) for unit vectors, so hard
// negative mining (min distance over different-label columns) == max dot.
// ---------------------------------------------------------------------------

#define BB   4096      // batch
#define DD   256       // feature dim
#define NCH  32        // column chunks (4096/128)

__device__ float g_an[BB * DD];              // normalized anchors      [B][D]
__device__ float g_pn[2 * BB * DD];          // normalized positives    [v][B][D]
__device__ float g_part[3 * NCH * BB];       // partial row maxima [mat][chunk][row]
__device__ float g_loss[BB];                 // per-row loss (both views summed)

// --------------------------- normalize ------------------------------------
__global__ void normalize_kernel(const float* __restrict__ anchor,
                                 const float* __restrict__ positive) {
    int warp = (blockIdx.x * blockDim.x + threadIdx.x) >> 5;
    int lane = threadIdx.x & 31;
    if (warp >= 3 * BB) return;

    const float* src;
    float* dst;
    if (warp < BB) {
        src = anchor + warp * DD;
        dst = g_an + warp * DD;
    } else {
        int r = warp - BB;          // r = i*2 + v
        int i = r >> 1, v = r & 1;
        src = positive + r * DD;
        dst = g_pn + (v * BB + i) * DD;
    }

    const float4* s4 = (const float4*)src;
    float4 x0 = s4[lane];
    float4 x1 = s4[lane + 32];
    float ss = x0.x * x0.x + x0.y * x0.y + x0.z * x0.z + x0.w * x0.w
             + x1.x * x1.x + x1.y * x1.y + x1.z * x1.z + x1.w * x1.w;
    #pragma unroll
    for (int o = 16; o >= 1; o >>= 1)
        ss += __shfl_xor_sync(0xffffffffu, ss, o);

    float inv = 1.0f / fmaxf(sqrtf(ss), 1e-12f);
    x0.x *= inv; x0.y *= inv; x0.z *= inv; x0.w *= inv;
    x1.x *= inv; x1.y *= inv; x1.z *= inv; x1.w *= inv;
    float4* d4 = (float4*)dst;
    d4[lane]      = x0;
    d4[lane + 32] = x1;
}

// --------------------------- fused GEMM + masked row max -------------------
// grid: (32 col-chunks, 32 row-tiles), 256 threads.
// Block tile 128x128, micro-tile 8x8 (strided: rows ty+16*rr, cols tx+16*cc).
// K-pair packed f32x2 FMAs: each LDS.128 yields two (k,k+1) 64-bit halves.
// Smem rows padded to 17 float4 (68 floats) -> conflict-free b-side LDS.128.

#define APITCH 17                       // float4 pitch per row (64+4 floats)
#define SMEM_BYTES (2 * 128 * APITCH * 16 + 128 * 4)

__global__ __launch_bounds__(256, 1)
void gemm_max_kernel(const int* __restrict__ labels) {
    extern __shared__ float smem[];
    float4* As4 = (float4*)smem;                    // [128][17]
    float4* Bs4 = As4 + 128 * APITCH;               // [128][17]
    int*    labc = (int*)(Bs4 + 128 * APITCH);      // [128]

    const int tid = threadIdx.x;
    const int tx = tid & 15, ty = tid >> 4;
    const int rowbase = blockIdx.y << 7;
    const int colbase = blockIdx.x << 7;

    if (tid < 128) labc[tid] = labels[colbase + tid];

    int rowlab[8];
    #pragma unroll
    for (int rr = 0; rr < 8; rr++)
        rowlab[rr] = labels[rowbase + ty + (rr << 4)];

    const float4* Ag = (const float4*)g_an;         // [4096][64] float4

    for (int m = 0; m < 3; m++) {
        const float4* Bg = (m == 0) ? (const float4*)g_an
                                    : (const float4*)(g_pn + (size_t)(m - 1) * BB * DD);

        unsigned long long acc[8][8];
        #pragma unroll
        for (int rr = 0; rr < 8; rr++)
            #pragma unroll
            for (int cc = 0; cc < 8; cc++)
                acc[rr][cc] = 0ull;

        for (int kt = 0; kt < 4; kt++) {
            __syncthreads();
            #pragma unroll
            for (int l = 0; l < 8; l++) {
                int idx = tid + (l << 8);            // 0..2047
                int r = idx >> 4, kq = idx & 15;
                As4[r * APITCH + kq] = Ag[((rowbase + r) << 6) + (kt << 4) + kq];
                Bs4[r * APITCH + kq] = Bg[((colbase + r) << 6) + (kt << 4) + kq];
            }
            __syncthreads();

            #pragma unroll
            for (int kq = 0; kq < 16; kq++) {
                ulonglong2 a[8];
                #pragma unroll
                for (int rr = 0; rr < 8; rr++)
                    a[rr] = *(const ulonglong2*)&As4[(ty + (rr << 4)) * APITCH + kq];
                #pragma unroll
                for (int cc = 0; cc < 8; cc++) {
                    ulonglong2 b = *(const ulonglong2*)&Bs4[(tx + (cc << 4)) * APITCH + kq];
                    #pragma unroll
                    for (int rr = 0; rr < 8; rr++) {
                        asm("fma.rn.f32x2 %0, %1, %2, %0;"
                            : "+l"(acc[rr][cc]) : "l"(a[rr].x), "l"(b.x));
                        asm("fma.rn.f32x2 %0, %1, %2, %0;"
                            : "+l"(acc[rr][cc]) : "l"(a[rr].y), "l"(b.y));
                    }
                }
            }
        }

        // Epilogue: per-row masked max over this block's 128 columns
        #pragma unroll
        for (int rr = 0; rr < 8; rr++) {
            float mx = -1e30f;
            #pragma unroll
            for (int cc = 0; cc < 8; cc++) {
                unsigned int lo = (unsigned int)(acc[rr][cc] & 0xffffffffull);
                unsigned int hi = (unsigned int)(acc[rr][cc] >> 32);
                float d = __uint_as_float(lo) + __uint_as_float(hi);
                if (labc[tx + (cc << 4)] != rowlab[rr]) mx = fmaxf(mx, d);
            }
            #pragma unroll
            for (int o = 8; o >= 1; o >>= 1)
                mx = fmaxf(mx, __shfl_xor_sync(0xffffffffu, mx, o));
            if (tx == 0)
                g_part[(m * NCH + blockIdx.x) * BB + rowbase + ty + (rr << 4)] = mx;
        }
    }
}

// --------------------------- per-row loss ----------------------------------
__global__ void finalize_kernel(void) {
    int warp = (blockIdx.x * blockDim.x + threadIdx.x) >> 5;
    int lane = threadIdx.x & 31;
    if (warp >= BB) return;
    int i = warp;

    // reduce chunk maxima (32 chunks -> 32 lanes)
    float ma = g_part[(0 * NCH + lane) * BB + i];
    float m0 = g_part[(1 * NCH + lane) * BB + i];
    float m1 = g_part[(2 * NCH + lane) * BB + i];
    #pragma unroll
    for (int o = 16; o >= 1; o >>= 1) {
        ma = fmaxf(ma, __shfl_xor_sync(0xffffffffu, ma, o));
        m0 = fmaxf(m0, __shfl_xor_sync(0xffffffffu, m0, o));
        m1 = fmaxf(m1, __shfl_xor_sync(0xffffffffu, m1, o));
    }

    // positive-pair dots
    const float4* a4  = (const float4*)(g_an + (size_t)i * DD);
    const float4* p04 = (const float4*)(g_pn + (size_t)i * DD);
    const float4* p14 = (const float4*)(g_pn + (size_t)(BB + i) * DD);
    float d0 = 0.f, d1 = 0.f;
    #pragma unroll
    for (int t = lane; t < 64; t += 32) {
        float4 av = a4[t], p0v = p04[t], p1v = p14[t];
        d0 += av.x * p0v.x + av.y * p0v.y + av.z * p0v.z + av.w * p0v.w;
        d1 += av.x * p1v.x + av.y * p1v.y + av.z * p1v.z + av.w * p1v.w;
    }
    #pragma unroll
    for (int o = 16; o >= 1; o >>= 1) {
        d0 += __shfl_xor_sync(0xffffffffu, d0, o);
        d1 += __shfl_xor_sync(0xffffffffu, d1, o);
    }

    if (lane == 0) {
        float neg0 = sqrtf(fmaxf(2.f - 2.f * fmaxf(ma, m0), 1e-12f));
        float neg1 = sqrtf(fmaxf(2.f - 2.f * fmaxf(ma, m1), 1e-12f));
        float pos0 = sqrtf(fmaxf(2.f - 2.f * d0, 1e-12f));
        float pos1 = sqrtf(fmaxf(2.f - 2.f * d1, 1e-12f));
        float l = fmaxf(pos0 - neg0 + 1.0f, 0.0f)
                + fmaxf(pos1 - neg1 + 1.0f, 0.0f);
        g_loss[i] = l;
    }
}

// --------------------------- deterministic final reduce --------------------
__global__ void reduce_kernel(float* __restrict__ out) {
    __shared__ float s[256];
    float v = 0.f;
    for (int i = threadIdx.x; i < BB; i += 256) v += g_loss[i];
    s[threadIdx.x] = v;
    __syncthreads();
    #pragma unroll
    for (int o = 128; o >= 1; o >>= 1) {
        if (threadIdx.x < o) s[threadIdx.x] += s[threadIdx.x + o];
        __syncthreads();
    }
    if (threadIdx.x == 0) out[0] = s[0] * (1.0f / (2.0f * BB));
}

// ---------------------------------------------------------------------------
extern "C" void kernel_launch(void* const* d_in, const int* in_sizes, int n_in,
                              void* d_out, int out_size) {
    const float* anchor = nullptr;
    const float* positive = nullptr;
    const int*   labels = nullptr;
    for (int i = 0; i < n_in; i++) {
        if (in_sizes[i] == BB * DD)          anchor   = (const float*)d_in[i];
        else if (in_sizes[i] == 2 * BB * DD) positive = (const float*)d_in[i];
        else if (in_sizes[i] == BB)          labels   = (const int*)d_in[i];
    }

    normalize_kernel<<<1536, 256>>>(anchor, positive);

    cudaFuncSetAttribute(gemm_max_kernel,
                         cudaFuncAttributeMaxDynamicSharedMemorySize, SMEM_BYTES);
    gemm_max_kernel<<<dim3(NCH, 32), 256, SMEM_BYTES>>>(labels);

    finalize_kernel<<<512, 256>>>();
    reduce_kernel<<<1, 256>>>((float*)d_out);
}

// round 3
// speedup vs baseline: 1.5654x; 1.5654x over previous
#include <cuda_runtime.h>
#include <cuda_bf16.h>
#include <cstdint>

// ---------------------------------------------------------------------------
// MultiViewTripletLoss: dist(x,y)=sqrt(2-2 x.y) for unit vectors; hard-negative
// mining == masked row-max of dot products.  One bf16 GEMM, K=768 split trick:
//   A-side rows [hi,hi,lo], B-side rows [hi,lo,hi]
//   => dot = hi.hi + hi.lo + lo.hi   (lo.lo dropped, ~2e-7)
// Engine: mma.sync.m16n8k16 (compute_103-base safe; tcgen05 needs sm_103a PTX
// target which this harness does not emit).
// ---------------------------------------------------------------------------

#define BB    4096
#define DD    256
#define K3    768
#define TM    128
#define TN    256
#define NCT   16           // col tiles per matrix (4096/256)
#define NSTG  24           // K stages (768/32)
#define PITCH 80           // smem row pitch bytes (64 data + 16 pad)

__device__ __align__(16) __nv_bfloat16 g_Xa[(size_t)BB * K3];
__device__ __align__(16) __nv_bfloat16 g_Xb[(size_t)3 * BB * K3];
__device__ float g_part[3 * NCT * BB];
__device__ float g_pos[2 * BB];
__device__ float g_loss[BB];

// smem map: labc[256] @0 | labr[128] @1024 | wmax @1536 | wpos @3584 |
//           stages @5632 (3 x 30720)
#define SM_LABC 0
#define SM_LABR 1024
#define SM_WMAX 1536
#define SM_WPOS 3584
#define SM_STG  5632
#define STG_SZ  30720
#define SM_A(b) (SM_STG + (b) * STG_SZ)
#define SM_B(b) (SM_A(b) + TM * PITCH)
#define SMEM_TOTAL (SM_STG + 3 * STG_SZ)

__device__ __forceinline__ uint32_t smem_u32(const void* p) {
    uint32_t a;
    asm("{ .reg .u64 t; cvta.to.shared.u64 t, %1; cvt.u32.u64 %0, t; }"
        : "=r"(a) : "l"(p));
    return a;
}
#define CP16(dst, src) \
    asm volatile("cp.async.cg.shared.global [%0], [%1], 16;" :: "r"(dst), "l"(src))
#define CP_COMMIT() asm volatile("cp.async.commit_group;" ::: "memory")
#define CP_WAIT(n)  asm volatile("cp.async.wait_group %0;" :: "n"(n) : "memory")
#define LDM4(r, a) \
    asm volatile("ldmatrix.sync.aligned.m8n8.x4.shared.b16 {%0,%1,%2,%3}, [%4];" \
        : "=r"((r)[0]), "=r"((r)[1]), "=r"((r)[2]), "=r"((r)[3]) : "r"(a))
#define MMA(d, a, b0, b1) \
    asm volatile("mma.sync.aligned.m16n8k16.row.col.f32.bf16.bf16.f32 " \
        "{%0,%1,%2,%3}, {%4,%5,%6,%7}, {%8,%9}, {%0,%1,%2,%3};" \
        : "+f"((d)[0]), "+f"((d)[1]), "+f"((d)[2]), "+f"((d)[3]) \
        : "r"((a)[0]), "r"((a)[1]), "r"((a)[2]), "r"((a)[3]), "r"(b0), "r"(b1))

// --------------------------- normalize + split -----------------------------
__global__ void norm_split_kernel(const float* __restrict__ anchor,
                                  const float* __restrict__ positive) {
    int warp = (blockIdx.x * blockDim.x + threadIdx.x) >> 5;
    int lane = threadIdx.x & 31;
    if (warp >= 3 * BB) return;

    const float* src;
    __nv_bfloat162* xa = nullptr;
    __nv_bfloat162* xb;
    if (warp < BB) {
        src = anchor + (size_t)warp * DD;
        xa = (__nv_bfloat162*)(g_Xa + (size_t)warp * K3);
        xb = (__nv_bfloat162*)(g_Xb + (size_t)warp * K3);
    } else {
        int r = warp - BB, i = r >> 1, v = r & 1;
        src = positive + (size_t)r * DD;
        xb = (__nv_bfloat162*)(g_Xb + (size_t)(BB + v * BB + i) * K3);
    }

    const float4* s4 = (const float4*)src;
    float4 x0 = s4[lane], x1 = s4[lane + 32];
    float ss = x0.x*x0.x + x0.y*x0.y + x0.z*x0.z + x0.w*x0.w
             + x1.x*x1.x + x1.y*x1.y + x1.z*x1.z + x1.w*x1.w;
    #pragma unroll
    for (int o = 16; o >= 1; o >>= 1) ss += __shfl_xor_sync(0xffffffffu, ss, o);
    float inv = 1.0f / fmaxf(sqrtf(ss), 1e-12f);

    float v8[8] = { x0.x*inv, x0.y*inv, x0.z*inv, x0.w*inv,
                    x1.x*inv, x1.y*inv, x1.z*inv, x1.w*inv };
    __nv_bfloat162 h[4], l[4];
    #pragma unroll
    for (int t = 0; t < 4; t++) {
        float a = v8[2*t], b = v8[2*t+1];
        __nv_bfloat16 ha = __float2bfloat16(a), hb = __float2bfloat16(b);
        __nv_bfloat16 la = __float2bfloat16(a - __bfloat162float(ha));
        __nv_bfloat16 lb = __float2bfloat16(b - __bfloat162float(hb));
        h[t] = __nv_bfloat162(ha, hb);
        l[t] = __nv_bfloat162(la, lb);
    }
    int c0 = 2 * lane, c1 = 64 + 2 * lane;
    #pragma unroll
    for (int t = 0; t < 2; t++) {
        int c = c0 + t;
        if (xa) { xa[c] = h[t]; xa[128 + c] = h[t]; xa[256 + c] = l[t]; }
        xb[c] = h[t]; xb[128 + c] = l[t]; xb[256 + c] = h[t];
    }
    #pragma unroll
    for (int t = 0; t < 2; t++) {
        int c = c1 + t;
        if (xa) { xa[c] = h[2+t]; xa[128 + c] = h[2+t]; xa[256 + c] = l[2+t]; }
        xb[c] = h[2+t]; xb[128 + c] = l[2+t]; xb[256 + c] = h[2+t];
    }
}

// --------------------------- GEMM + masked row max -------------------------
__device__ __forceinline__ void load_stage(uint32_t sb, int buf, int s,
                                           int rowbase, int colbase, int tid) {
    const char* Ag = (const char*)g_Xa;
    const char* Bg = (const char*)g_Xb;
    {
        int row = tid & 127, ch = tid >> 7;                 // 512 chunks
        uint32_t dst = sb + SM_A(buf) + row * PITCH + ch * 16;
        const char* src = Ag + (size_t)(rowbase + row) * (K3 * 2) + s * 64 + ch * 16;
        CP16(dst, src);
    }
    #pragma unroll
    for (int lp = 0; lp < 2; lp++) {                        // 1024 chunks
        int idx = tid + (lp << 9);
        int row = idx & 255, ch = idx >> 8;
        uint32_t dst = sb + SM_B(buf) + row * PITCH + ch * 16;
        const char* src = Bg + (size_t)(colbase + row) * (K3 * 2) + s * 64 + ch * 16;
        CP16(dst, src);
    }
    CP_COMMIT();
}

__global__ __launch_bounds__(512, 1)
void gemm_max_kernel(const int* __restrict__ labels) {
    extern __shared__ char smem[];
    uint32_t sb = smem_u32(smem);
    int* labc = (int*)(smem + SM_LABC);
    int* labr = (int*)(smem + SM_LABR);
    float* wmax = (float*)(smem + SM_WMAX);
    float* wpos = (float*)(smem + SM_WPOS);

    const int tid = threadIdx.x;
    const int lane = tid & 31;
    const int wid = tid >> 5;
    const int wm = wid >> 2, wn = wid & 3;
    const int rowbase = blockIdx.y * TM;
    const int colbase = blockIdx.x * TN;           // row index into g_Xb
    const int m  = blockIdx.x >> 4;                // matrix (0=A,1=P0,2=P1)
    const int ct = blockIdx.x & 15;
    const int cibase = ct << 8;                    // col base within matrix

    if (tid < 256) labc[tid] = labels[cibase + tid];
    if (tid < 128) labr[tid] = labels[rowbase + tid];

    float acc[2][8][4];
    #pragma unroll
    for (int i = 0; i < 2; i++)
        #pragma unroll
        for (int j = 0; j < 8; j++)
            #pragma unroll
            for (int k = 0; k < 4; k++) acc[i][j][k] = 0.f;

    load_stage(sb, 0, 0, rowbase, colbase, tid);
    load_stage(sb, 1, 1, rowbase, colbase, tid);

    // ldmatrix base addresses (per-lane), offsets added per tile/kstep
    const uint32_t a_off = (wm * 32 + (lane & 15)) * PITCH + ((lane >> 4) & 1) * 16;
    const uint32_t b_off = (wn * 64 + (lane & 7) + ((lane >> 4) & 1) * 8) * PITCH
                         + ((lane >> 3) & 1) * 16;

    for (int s = 0; s < NSTG; s++) {
        int buf = s % 3;
        CP_WAIT(1);
        __syncthreads();

        uint32_t ab = sb + SM_A(buf) + a_off;
        uint32_t bb = sb + SM_B(buf) + b_off;
        #pragma unroll
        for (int ks = 0; ks < 2; ks++) {
            uint32_t af[2][4];
            LDM4(af[0], ab + ks * 32);
            LDM4(af[1], ab + ks * 32 + 16 * PITCH);
            #pragma unroll
            for (int np = 0; np < 4; np++) {
                uint32_t bf[4];
                LDM4(bf, bb + ks * 32 + np * 16 * PITCH);
                MMA(acc[0][2*np],   af[0], bf[0], bf[1]);
                MMA(acc[0][2*np+1], af[0], bf[2], bf[3]);
                MMA(acc[1][2*np],   af[1], bf[0], bf[1]);
                MMA(acc[1][2*np+1], af[1], bf[2], bf[3]);
            }
        }
        __syncthreads();
        if (s + 2 < NSTG)
            load_stage(sb, (s + 2) % 3, s + 2, rowbase, colbase, tid);
    }

    // ---------------- epilogue: masked row max + diagonal positives --------
    #pragma unroll
    for (int mi = 0; mi < 2; mi++) {
        #pragma unroll
        for (int hi = 0; hi < 2; hi++) {
            int lr = wm * 32 + mi * 16 + hi * 8 + (lane >> 2);
            int rlab = labr[lr];
            int grow = rowbase + lr;
            float mx = -1e30f, pv = 0.f;
            #pragma unroll
            for (int ni = 0; ni < 8; ni++) {
                int c = wn * 64 + ni * 8 + 2 * (lane & 3);
                float v0 = acc[mi][ni][hi * 2 + 0];
                float v1 = acc[mi][ni][hi * 2 + 1];
                if (labc[c]     != rlab) mx = fmaxf(mx, v0);
                if (labc[c + 1] != rlab) mx = fmaxf(mx, v1);
                if (m > 0) {
                    if (cibase + c == grow)     pv += v0;
                    if (cibase + c + 1 == grow) pv += v1;
                }
            }
            mx = fmaxf(mx, __shfl_xor_sync(0xffffffffu, mx, 1));
            mx = fmaxf(mx, __shfl_xor_sync(0xffffffffu, mx, 2));
            pv += __shfl_xor_sync(0xffffffffu, pv, 1);
            pv += __shfl_xor_sync(0xffffffffu, pv, 2);
            if ((lane & 3) == 0) {
                wmax[wn * 128 + lr] = mx;
                wpos[wn * 128 + lr] = pv;
            }
        }
    }
    __syncthreads();
    if (tid < 128) {
        float mx = fmaxf(fmaxf(wmax[tid], wmax[128 + tid]),
                         fmaxf(wmax[256 + tid], wmax[384 + tid]));
        g_part[(m * NCT + ct) * BB + rowbase + tid] = mx;
        if (m > 0) {
            int grow = rowbase + tid;
            if (grow >= cibase && grow < cibase + TN) {
                float pv = wpos[tid] + wpos[128 + tid]
                         + wpos[256 + tid] + wpos[384 + tid];
                g_pos[(m - 1) * BB + grow] = pv;
            }
        }
    }
}

// --------------------------- finalize + reduce -----------------------------
__global__ void finalize_kernel(void) {
    int i = blockIdx.x * blockDim.x + threadIdx.x;
    if (i >= BB) return;
    float ma = -1e30f, m0 = -1e30f, m1 = -1e30f;
    #pragma unroll
    for (int c = 0; c < NCT; c++) {
        ma = fmaxf(ma, g_part[(0 * NCT + c) * BB + i]);
        m0 = fmaxf(m0, g_part[(1 * NCT + c) * BB + i]);
        m1 = fmaxf(m1, g_part[(2 * NCT + c) * BB + i]);
    }
    float d0 = g_pos[i], d1 = g_pos[BB + i];
    float neg0 = sqrtf(fmaxf(2.f - 2.f * fmaxf(ma, m0), 1e-12f));
    float neg1 = sqrtf(fmaxf(2.f - 2.f * fmaxf(ma, m1), 1e-12f));
    float pos0 = sqrtf(fmaxf(2.f - 2.f * d0, 1e-12f));
    float pos1 = sqrtf(fmaxf(2.f - 2.f * d1, 1e-12f));
    g_loss[i] = fmaxf(pos0 - neg0 + 1.0f, 0.0f) + fmaxf(pos1 - neg1 + 1.0f, 0.0f);
}

__global__ void reduce_kernel(float* __restrict__ out) {
    __shared__ float s[256];
    float v = 0.f;
    for (int i = threadIdx.x; i < BB; i += 256) v += g_loss[i];
    s[threadIdx.x] = v;
    __syncthreads();
    #pragma unroll
    for (int o = 128; o >= 1; o >>= 1) {
        if (threadIdx.x < o) s[threadIdx.x] += s[threadIdx.x + o];
        __syncthreads();
    }
    if (threadIdx.x == 0) out[0] = s[0] * (1.0f / (2.0f * BB));
}

// ---------------------------------------------------------------------------
extern "C" void kernel_launch(void* const* d_in, const int* in_sizes, int n_in,
                              void* d_out, int out_size) {
    const float* anchor = nullptr;
    const float* positive = nullptr;
    const int*   labels = nullptr;
    for (int i = 0; i < n_in; i++) {
        if (in_sizes[i] == BB * DD)          anchor   = (const float*)d_in[i];
        else if (in_sizes[i] == 2 * BB * DD) positive = (const float*)d_in[i];
        else if (in_sizes[i] == BB)          labels   = (const int*)d_in[i];
    }

    norm_split_kernel<<<1536, 256>>>(anchor, positive);

    cudaFuncSetAttribute(gemm_max_kernel,
                         cudaFuncAttributeMaxDynamicSharedMemorySize, SMEM_TOTAL);
    gemm_max_kernel<<<dim3(3 * NCT, BB / TM), 512, SMEM_TOTAL>>>(labels);

    finalize_kernel<<<16, 256>>>();
    reduce_kernel<<<1, 256>>>((float*)d_out);
}

// round 5
// speedup vs baseline: 3.9395x; 2.5166x over previous
#include <cuda_runtime.h>
#include <cuda_fp16.h>
#include <cstdint>

// ---------------------------------------------------------------------------
// MultiViewTripletLoss: dist(x,y)=sqrt(2-2 x.y) for unit vectors; hard-negative
// mining == masked row-max of dot products.  Single fp16 GEMM (K=256):
// fp16 quantization of unit vectors gives dot error sigma ~1e-5, max-mining
// bias ~5e-5 -> ~25x under the 1e-3 gate.  Engine: mma.sync.m16n8k16
// (compute_103-base safe; tcgen05 is sm_103a-target-only, unavailable here).
// ---------------------------------------------------------------------------

#define BB    4096
#define DD    256
#define TM    128
#define TN    256
#define NCT   16           // col tiles per matrix (4096/256)
#define NSTG  8            // K stages (256/32)
#define PITCH 80           // smem row pitch bytes (64 data + 16 pad)

__device__ __align__(16) __half g_X[(size_t)3 * BB * DD];   // [m][row][k]
__device__ float g_part[3 * NCT * BB];
__device__ float g_pos[2 * BB];

// smem map: labc[256] @0 | labr[128] @1024 | wmax @1536 | wpos @3584 |
//           stages @5632 (3 x 30720)
#define SM_LABC 0
#define SM_LABR 1024
#define SM_WMAX 1536
#define SM_WPOS 3584
#define SM_STG  5632
#define STG_SZ  30720
#define SM_A(b) (SM_STG + (b) * STG_SZ)
#define SM_B(b) (SM_A(b) + TM * PITCH)
#define SMEM_TOTAL (SM_STG + 3 * STG_SZ)

__device__ __forceinline__ uint32_t smem_u32(const void* p) {
    uint32_t a;
    asm("{ .reg .u64 t; cvta.to.shared.u64 t, %1; cvt.u32.u64 %0, t; }"
        : "=r"(a) : "l"(p));
    return a;
}
#define CP16(dst, src) \
    asm volatile("cp.async.cg.shared.global [%0], [%1], 16;" :: "r"(dst), "l"(src))
#define CP_COMMIT() asm volatile("cp.async.commit_group;" ::: "memory")
#define CP_WAIT(n)  asm volatile("cp.async.wait_group %0;" :: "n"(n) : "memory")
#define LDM4(r, a) \
    asm volatile("ldmatrix.sync.aligned.m8n8.x4.shared.b16 {%0,%1,%2,%3}, [%4];" \
        : "=r"((r)[0]), "=r"((r)[1]), "=r"((r)[2]), "=r"((r)[3]) : "r"(a))
#define MMA(d, a, b0, b1) \
    asm volatile("mma.sync.aligned.m16n8k16.row.col.f32.f16.f16.f32 " \
        "{%0,%1,%2,%3}, {%4,%5,%6,%7}, {%8,%9}, {%0,%1,%2,%3};" \
        : "+f"((d)[0]), "+f"((d)[1]), "+f"((d)[2]), "+f"((d)[3]) \
        : "r"((a)[0]), "r"((a)[1]), "r"((a)[2]), "r"((a)[3]), "r"(b0), "r"(b1))

// --------------------------- normalize -> fp16 -----------------------------
__global__ void norm_kernel(const float* __restrict__ anchor,
                            const float* __restrict__ positive) {
    int warp = (blockIdx.x * blockDim.x + threadIdx.x) >> 5;
    int lane = threadIdx.x & 31;
    if (warp >= 3 * BB) return;

    const float* src;
    __half2* dst;
    if (warp < BB) {
        src = anchor + (size_t)warp * DD;
        dst = (__half2*)(g_X + (size_t)warp * DD);
    } else {
        int r = warp - BB, i = r >> 1, v = r & 1;   // r = i*2 + v
        src = positive + (size_t)r * DD;
        dst = (__half2*)(g_X + (size_t)((1 + v) * BB + i) * DD);
    }

    const float4* s4 = (const float4*)src;
    float4 x0 = s4[lane], x1 = s4[lane + 32];
    float ss = x0.x*x0.x + x0.y*x0.y + x0.z*x0.z + x0.w*x0.w
             + x1.x*x1.x + x1.y*x1.y + x1.z*x1.z + x1.w*x1.w;
    #pragma unroll
    for (int o = 16; o >= 1; o >>= 1) ss += __shfl_xor_sync(0xffffffffu, ss, o);
    float inv = 1.0f / fmaxf(sqrtf(ss), 1e-12f);

    dst[2*lane]      = __floats2half2_rn(x0.x*inv, x0.y*inv);
    dst[2*lane + 1]  = __floats2half2_rn(x0.z*inv, x0.w*inv);
    dst[64 + 2*lane] = __floats2half2_rn(x1.x*inv, x1.y*inv);
    dst[65 + 2*lane] = __floats2half2_rn(x1.z*inv, x1.w*inv);
}

// --------------------------- GEMM + masked row max -------------------------
__device__ __forceinline__ void load_stage(uint32_t sb, int buf, int s,
                                           int rowbase, int colrowbase, int tid) {
    const char* Xg = (const char*)g_X;
    {
        int row = tid & 127, ch = tid >> 7;                 // 512 chunks (A)
        uint32_t dst = sb + SM_A(buf) + row * PITCH + ch * 16;
        const char* src = Xg + (size_t)(rowbase + row) * (DD * 2) + s * 64 + ch * 16;
        CP16(dst, src);
    }
    #pragma unroll
    for (int lp = 0; lp < 2; lp++) {                        // 1024 chunks (B)
        int idx = tid + (lp << 9);
        int row = idx & 255, ch = idx >> 8;
        uint32_t dst = sb + SM_B(buf) + row * PITCH + ch * 16;
        const char* src = Xg + (size_t)(colrowbase + row) * (DD * 2) + s * 64 + ch * 16;
        CP16(dst, src);
    }
    CP_COMMIT();
}

__global__ __launch_bounds__(512, 1)
void gemm_max_kernel(const int* __restrict__ labels) {
    extern __shared__ char smem[];
    uint32_t sb = smem_u32(smem);
    int* labc = (int*)(smem + SM_LABC);
    int* labr = (int*)(smem + SM_LABR);
    float* wmax = (float*)(smem + SM_WMAX);
    float* wpos = (float*)(smem + SM_WPOS);

    const int tid = threadIdx.x;
    const int lane = tid & 31;
    const int wid = tid >> 5;
    const int wm = wid >> 2, wn = wid & 3;
    const int rowbase = blockIdx.y * TM;
    const int colrowbase = blockIdx.x * TN;        // row index into g_X
    const int m  = blockIdx.x >> 4;                // matrix (0=A,1=P0,2=P1)
    const int ct = blockIdx.x & 15;
    const int cibase = ct << 8;                    // col base within matrix

    if (tid < 256) labc[tid] = labels[cibase + tid];
    if (tid < 128) labr[tid] = labels[rowbase + tid];

    float acc[2][8][4];
    #pragma unroll
    for (int i = 0; i < 2; i++)
        #pragma unroll
        for (int j = 0; j < 8; j++)
            #pragma unroll
            for (int k = 0; k < 4; k++) acc[i][j][k] = 0.f;

    load_stage(sb, 0, 0, rowbase, colrowbase, tid);
    load_stage(sb, 1, 1, rowbase, colrowbase, tid);

    const uint32_t a_off = (wm * 32 + (lane & 15)) * PITCH + ((lane >> 4) & 1) * 16;
    const uint32_t b_off = (wn * 64 + (lane & 7) + ((lane >> 4) & 1) * 8) * PITCH
                         + ((lane >> 3) & 1) * 16;

    for (int s = 0; s < NSTG; s++) {
        int buf = s % 3;
        CP_WAIT(1);
        __syncthreads();

        uint32_t ab = sb + SM_A(buf) + a_off;
        uint32_t bb = sb + SM_B(buf) + b_off;
        #pragma unroll
        for (int ks = 0; ks < 2; ks++) {
            uint32_t af[2][4];
            LDM4(af[0], ab + ks * 32);
            LDM4(af[1], ab + ks * 32 + 16 * PITCH);
            #pragma unroll
            for (int np = 0; np < 4; np++) {
                uint32_t bf[4];
                LDM4(bf, bb + ks * 32 + np * 16 * PITCH);
                MMA(acc[0][2*np],   af[0], bf[0], bf[1]);
                MMA(acc[0][2*np+1], af[0], bf[2], bf[3]);
                MMA(acc[1][2*np],   af[1], bf[0], bf[1]);
                MMA(acc[1][2*np+1], af[1], bf[2], bf[3]);
            }
        }
        __syncthreads();
        if (s + 2 < NSTG)
            load_stage(sb, (s + 2) % 3, s + 2, rowbase, colrowbase, tid);
    }

    // ---------------- epilogue: masked row max + diagonal positives --------
    #pragma unroll
    for (int mi = 0; mi < 2; mi++) {
        #pragma unroll
        for (int hi = 0; hi < 2; hi++) {
            int lr = wm * 32 + mi * 16 + hi * 8 + (lane >> 2);
            int rlab = labr[lr];
            int grow = rowbase + lr;
            float mx = -1e30f, pv = 0.f;
            #pragma unroll
            for (int ni = 0; ni < 8; ni++) {
                int c = wn * 64 + ni * 8 + 2 * (lane & 3);
                float v0 = acc[mi][ni][hi * 2 + 0];
                float v1 = acc[mi][ni][hi * 2 + 1];
                if (labc[c]     != rlab) mx = fmaxf(mx, v0);
                if (labc[c + 1] != rlab) mx = fmaxf(mx, v1);
                if (m > 0) {
                    if (cibase + c == grow)     pv += v0;
                    if (cibase + c + 1 == grow) pv += v1;
                }
            }
            mx = fmaxf(mx, __shfl_xor_sync(0xffffffffu, mx, 1));
            mx = fmaxf(mx, __shfl_xor_sync(0xffffffffu, mx, 2));
            pv += __shfl_xor_sync(0xffffffffu, pv, 1);
            pv += __shfl_xor_sync(0xffffffffu, pv, 2);
            if ((lane & 3) == 0) {
                wmax[wn * 128 + lr] = mx;
                wpos[wn * 128 + lr] = pv;
            }
        }
    }
    __syncthreads();
    if (tid < 128) {
        float mx = fmaxf(fmaxf(wmax[tid], wmax[128 + tid]),
                         fmaxf(wmax[256 + tid], wmax[384 + tid]));
        g_part[(m * NCT + ct) * BB + rowbase + tid] = mx;
        if (m > 0) {
            int grow = rowbase + tid;
            if (grow >= cibase && grow < cibase + TN) {
                float pv = wpos[tid] + wpos[128 + tid]
                         + wpos[256 + tid] + wpos[384 + tid];
                g_pos[(m - 1) * BB + grow] = pv;
            }
        }
    }
}

// ------------------- fused finalize + deterministic reduce -----------------
__global__ __launch_bounds__(1024, 1)
void finalize_reduce_kernel(float* __restrict__ out) {
    __shared__ float s[1024];
    float tot = 0.f;
    #pragma unroll
    for (int r = 0; r < 4; r++) {
        int i = threadIdx.x + (r << 10);
        float ma = -1e30f, m0 = -1e30f, m1 = -1e30f;
        #pragma unroll
        for (int c = 0; c < NCT; c++) {
            ma = fmaxf(ma, g_part[(0 * NCT + c) * BB + i]);
            m0 = fmaxf(m0, g_part[(1 * NCT + c) * BB + i]);
            m1 = fmaxf(m1, g_part[(2 * NCT + c) * BB + i]);
        }
        float d0 = g_pos[i], d1 = g_pos[BB + i];
        float neg0 = sqrtf(fmaxf(2.f - 2.f * fmaxf(ma, m0), 1e-12f));
        float neg1 = sqrtf(fmaxf(2.f - 2.f * fmaxf(ma, m1), 1e-12f));
        float pos0 = sqrtf(fmaxf(2.f - 2.f * d0, 1e-12f));
        float pos1 = sqrtf(fmaxf(2.f - 2.f * d1, 1e-12f));
        tot += fmaxf(pos0 - neg0 + 1.0f, 0.0f) + fmaxf(pos1 - neg1 + 1.0f, 0.0f);
    }
    s[threadIdx.x] = tot;
    __syncthreads();
    #pragma unroll
    for (int o = 512; o >= 1; o >>= 1) {
        if (threadIdx.x < o) s[threadIdx.x] += s[threadIdx.x + o];
        __syncthreads();
    }
    if (threadIdx.x == 0) out[0] = s[0] * (1.0f / (2.0f * BB));
}

// ---------------------------------------------------------------------------
extern "C" void kernel_launch(void* const* d_in, const int* in_sizes, int n_in,
                              void* d_out, int out_size) {
    const float* anchor = nullptr;
    const float* positive = nullptr;
    const int*   labels = nullptr;
    for (int i = 0; i < n_in; i++) {
        if (in_sizes[i] == BB * DD)          anchor   = (const float*)d_in[i];
        else if (in_sizes[i] == 2 * BB * DD) positive = (const float*)d_in[i];
        else if (in_sizes[i] == BB)          labels   = (const int*)d_in[i];
    }

    norm_kernel<<<1536, 256>>>(anchor, positive);

    cudaFuncSetAttribute(gemm_max_kernel,
                         cudaFuncAttributeMaxDynamicSharedMemorySize, SMEM_TOTAL);
    gemm_max_kernel<<<dim3(3 * NCT, BB / TM), 512, SMEM_TOTAL>>>(labels);

    finalize_reduce_kernel<<<1, 1024>>>((float*)d_out);
}

// round 6
// speedup vs baseline: 5.8704x; 1.4901x over previous
#include <cuda_runtime.h>
#include <cuda_fp16.h>
#include <cstdint>

// ---------------------------------------------------------------------------
// MultiViewTripletLoss: dist(x,y)=sqrt(2-2 x.y) for unit vectors; hard-negative
// mining == masked row-max of dot products.  Single fp16 GEMM (K=256),
// mma.sync.m16n8k16.  This round: 128x128 tiles / 256 threads => 2 CTAs/SM
// (hide sync bubbles), and flip-encoded atomicMax partial maxima (no g_part
// matrix, near-free finalize).
// ---------------------------------------------------------------------------

#define BB    4096
#define DD    256
#define TM    128
#define TN    128
#define NCT   32           // col tiles per matrix (4096/128)
#define NSTG  8            // K stages (256/32)
#define PITCH 80           // smem row pitch bytes (64 data + 16 pad)

__device__ __align__(16) __half g_X[(size_t)3 * BB * DD];   // [m][row][k]
__device__ unsigned int g_negbits[3 * BB];   // flip-encoded row maxima
__device__ float g_pos[2 * BB];              // positive-pair dots

// smem: labc[128] @0 | labr[128] @512 | stages @1024 (3 x 20480)
#define SM_LABC 0
#define SM_LABR 512
#define SM_STG  1024
#define STG_SZ  20480
#define SM_A(b) (SM_STG + (b) * STG_SZ)
#define SM_B(b) (SM_A(b) + TM * PITCH)
#define SMEM_TOTAL (SM_STG + 3 * STG_SZ)

__device__ __forceinline__ uint32_t smem_u32(const void* p) {
    uint32_t a;
    asm("{ .reg .u64 t; cvta.to.shared.u64 t, %1; cvt.u32.u64 %0, t; }"
        : "=r"(a) : "l"(p));
    return a;
}
#define CP16(dst, src) \
    asm volatile("cp.async.cg.shared.global [%0], [%1], 16;" :: "r"(dst), "l"(src))
#define CP_COMMIT() asm volatile("cp.async.commit_group;" ::: "memory")
#define CP_WAIT(n)  asm volatile("cp.async.wait_group %0;" :: "n"(n) : "memory")
#define LDM4(r, a) \
    asm volatile("ldmatrix.sync.aligned.m8n8.x4.shared.b16 {%0,%1,%2,%3}, [%4];" \
        : "=r"((r)[0]), "=r"((r)[1]), "=r"((r)[2]), "=r"((r)[3]) : "r"(a))
#define MMA(d, a, b0, b1) \
    asm volatile("mma.sync.aligned.m16n8k16.row.col.f32.f16.f16.f32 " \
        "{%0,%1,%2,%3}, {%4,%5,%6,%7}, {%8,%9}, {%0,%1,%2,%3};" \
        : "+f"((d)[0]), "+f"((d)[1]), "+f"((d)[2]), "+f"((d)[3]) \
        : "r"((a)[0]), "r"((a)[1]), "r"((a)[2]), "r"((a)[3]), "r"(b0), "r"(b1))

// monotone float <-> uint encoding for atomicMax over signed floats
__device__ __forceinline__ unsigned int fflip(float f) {
    unsigned int u = __float_as_uint(f);
    return u ^ (unsigned int)(((int)u >> 31) | 0x80000000);
}
__device__ __forceinline__ float funflip(unsigned int m) {
    unsigned int u = (m & 0x80000000u) ? (m ^ 0x80000000u) : ~m;
    return __uint_as_float(u);
}

// --------------------------- normalize -> fp16 (+ negbits init) ------------
__global__ void norm_kernel(const float* __restrict__ anchor,
                            const float* __restrict__ positive) {
    int warp = (blockIdx.x * blockDim.x + threadIdx.x) >> 5;
    int lane = threadIdx.x & 31;
    if (warp >= 3 * BB) return;
    if (lane == 0) g_negbits[warp] = 0u;     // == fflip(very negative)

    const float* src;
    __half2* dst;
    if (warp < BB) {
        src = anchor + (size_t)warp * DD;
        dst = (__half2*)(g_X + (size_t)warp * DD);
    } else {
        int r = warp - BB, i = r >> 1, v = r & 1;   // r = i*2 + v
        src = positive + (size_t)r * DD;
        dst = (__half2*)(g_X + (size_t)((1 + v) * BB + i) * DD);
    }

    const float4* s4 = (const float4*)src;
    float4 x0 = s4[lane], x1 = s4[lane + 32];
    float ss = x0.x*x0.x + x0.y*x0.y + x0.z*x0.z + x0.w*x0.w
             + x1.x*x1.x + x1.y*x1.y + x1.z*x1.z + x1.w*x1.w;
    #pragma unroll
    for (int o = 16; o >= 1; o >>= 1) ss += __shfl_xor_sync(0xffffffffu, ss, o);
    float inv = 1.0f / fmaxf(sqrtf(ss), 1e-12f);

    dst[2*lane]      = __floats2half2_rn(x0.x*inv, x0.y*inv);
    dst[2*lane + 1]  = __floats2half2_rn(x0.z*inv, x0.w*inv);
    dst[64 + 2*lane] = __floats2half2_rn(x1.x*inv, x1.y*inv);
    dst[65 + 2*lane] = __floats2half2_rn(x1.z*inv, x1.w*inv);
}

// --------------------------- GEMM + masked row max -------------------------
__device__ __forceinline__ void load_stage(uint32_t sb, int buf, int s,
                                           int rowbase, int colrowbase, int tid) {
    const char* Xg = (const char*)g_X;
    #pragma unroll
    for (int lp = 0; lp < 2; lp++) {                 // A: 512 chunks of 16B
        int idx = tid + (lp << 8);
        int row = idx >> 2, ch = idx & 3;
        uint32_t dst = sb + SM_A(buf) + row * PITCH + ch * 16;
        const char* src = Xg + (size_t)(rowbase + row) * (DD * 2) + s * 64 + ch * 16;
        CP16(dst, src);
    }
    #pragma unroll
    for (int lp = 0; lp < 2; lp++) {                 // B: 512 chunks of 16B
        int idx = tid + (lp << 8);
        int row = idx >> 2, ch = idx & 3;
        uint32_t dst = sb + SM_B(buf) + row * PITCH + ch * 16;
        const char* src = Xg + (size_t)(colrowbase + row) * (DD * 2) + s * 64 + ch * 16;
        CP16(dst, src);
    }
    CP_COMMIT();
}

__global__ __launch_bounds__(256, 2)
void gemm_max_kernel(const int* __restrict__ labels) {
    extern __shared__ char smem[];
    uint32_t sb = smem_u32(smem);
    int* labc = (int*)(smem + SM_LABC);
    int* labr = (int*)(smem + SM_LABR);

    const int tid = threadIdx.x;
    const int lane = tid & 31;
    const int wid = tid >> 5;
    const int wm = wid >> 2, wn = wid & 3;           // 2 x 4 warp grid
    const int rowbase = blockIdx.y * TM;
    const int colrowbase = blockIdx.x * TN;          // row index into g_X
    const int m  = blockIdx.x >> 5;                  // matrix (0=A,1=P0,2=P1)
    const int ct = blockIdx.x & 31;
    const int cibase = ct << 7;                      // col base within matrix

    if (tid < 128) {
        labc[tid] = labels[cibase + tid];
        labr[tid] = labels[rowbase + tid];
    }

    float acc[4][4][4];                              // [mi][ni][frag]
    #pragma unroll
    for (int i = 0; i < 4; i++)
        #pragma unroll
        for (int j = 0; j < 4; j++)
            #pragma unroll
            for (int k = 0; k < 4; k++) acc[i][j][k] = 0.f;

    load_stage(sb, 0, 0, rowbase, colrowbase, tid);
    load_stage(sb, 1, 1, rowbase, colrowbase, tid);

    // warp tile 64x32: A rows wm*64 + mi*16, B cols wn*32 + ni2*16
    const uint32_t a_off = (wm * 64 + (lane & 15)) * PITCH + ((lane >> 4) & 1) * 16;
    const uint32_t b_off = (wn * 32 + (lane & 7) + ((lane >> 4) & 1) * 8) * PITCH
                         + ((lane >> 3) & 1) * 16;

    for (int s = 0; s < NSTG; s++) {
        int buf = s % 3;
        CP_WAIT(1);
        __syncthreads();

        uint32_t ab = sb + SM_A(buf) + a_off;
        uint32_t bb = sb + SM_B(buf) + b_off;
        #pragma unroll
        for (int ks = 0; ks < 2; ks++) {
            uint32_t af[4][4];
            #pragma unroll
            for (int mi = 0; mi < 4; mi++)
                LDM4(af[mi], ab + ks * 32 + mi * 16 * PITCH);
            #pragma unroll
            for (int ni2 = 0; ni2 < 2; ni2++) {
                uint32_t bf[4];
                LDM4(bf, bb + ks * 32 + ni2 * 16 * PITCH);
                #pragma unroll
                for (int mi = 0; mi < 4; mi++) {
                    MMA(acc[mi][2*ni2],   af[mi], bf[0], bf[1]);
                    MMA(acc[mi][2*ni2+1], af[mi], bf[2], bf[3]);
                }
            }
        }
        __syncthreads();
        if (s + 2 < NSTG)
            load_stage(sb, (s + 2) % 3, s + 2, rowbase, colrowbase, tid);
    }

    // ------- epilogue: quad-reduce masked max, atomicMax partials ----------
    #pragma unroll
    for (int mi = 0; mi < 4; mi++) {
        #pragma unroll
        for (int hi = 0; hi < 2; hi++) {
            int lr = wm * 64 + mi * 16 + hi * 8 + (lane >> 2);
            int rlab = labr[lr];
            int grow = rowbase + lr;
            float mx = -1e30f, pv = 0.f;
            int match = 0;
            #pragma unroll
            for (int ni = 0; ni < 4; ni++) {
                int c = wn * 32 + ni * 8 + 2 * (lane & 3);
                float v0 = acc[mi][ni][hi * 2 + 0];
                float v1 = acc[mi][ni][hi * 2 + 1];
                if (labc[c]     != rlab) mx = fmaxf(mx, v0);
                if (labc[c + 1] != rlab) mx = fmaxf(mx, v1);
                if (m > 0) {
                    if (cibase + c == grow)     { pv += v0; match = 1; }
                    if (cibase + c + 1 == grow) { pv += v1; match = 1; }
                }
            }
            mx = fmaxf(mx, __shfl_xor_sync(0xffffffffu, mx, 1));
            mx = fmaxf(mx, __shfl_xor_sync(0xffffffffu, mx, 2));
            pv += __shfl_xor_sync(0xffffffffu, pv, 1);
            pv += __shfl_xor_sync(0xffffffffu, pv, 2);
            match |= __shfl_xor_sync(0xffffffffu, match, 1);
            match |= __shfl_xor_sync(0xffffffffu, match, 2);
            if ((lane & 3) == 0) {
                atomicMax(&g_negbits[m * BB + grow], fflip(mx));
                if (m > 0 && match) g_pos[(m - 1) * BB + grow] = pv;
            }
        }
    }
}

// ------------------- fused finalize + deterministic reduce -----------------
__global__ __launch_bounds__(1024, 1)
void finalize_reduce_kernel(float* __restrict__ out) {
    __shared__ float s[1024];
    float tot = 0.f;
    #pragma unroll
    for (int r = 0; r < 4; r++) {
        int i = threadIdx.x + (r << 10);
        float ma = funflip(g_negbits[i]);
        float m0 = funflip(g_negbits[BB + i]);
        float m1 = funflip(g_negbits[2 * BB + i]);
        float d0 = g_pos[i], d1 = g_pos[BB + i];
        float neg0 = sqrtf(fmaxf(2.f - 2.f * fmaxf(ma, m0), 1e-12f));
        float neg1 = sqrtf(fmaxf(2.f - 2.f * fmaxf(ma, m1), 1e-12f));
        float pos0 = sqrtf(fmaxf(2.f - 2.f * d0, 1e-12f));
        float pos1 = sqrtf(fmaxf(2.f - 2.f * d1, 1e-12f));
        tot += fmaxf(pos0 - neg0 + 1.0f, 0.0f) + fmaxf(pos1 - neg1 + 1.0f, 0.0f);
    }
    s[threadIdx.x] = tot;
    __syncthreads();
    #pragma unroll
    for (int o = 512; o >= 1; o >>= 1) {
        if (threadIdx.x < o) s[threadIdx.x] += s[threadIdx.x + o];
        __syncthreads();
    }
    if (threadIdx.x == 0) out[0] = s[0] * (1.0f / (2.0f * BB));
}

// ---------------------------------------------------------------------------
extern "C" void kernel_launch(void* const* d_in, const int* in_sizes, int n_in,
                              void* d_out, int out_size) {
    const float* anchor = nullptr;
    const float* positive = nullptr;
    const int*   labels = nullptr;
    for (int i = 0; i < n_in; i++) {
        if (in_sizes[i] == BB * DD)          anchor   = (const float*)d_in[i];
        else if (in_sizes[i] == 2 * BB * DD) positive = (const float*)d_in[i];
        else if (in_sizes[i] == BB)          labels   = (const int*)d_in[i];
    }

    norm_kernel<<<1536, 256>>>(anchor, positive);

    cudaFuncSetAttribute(gemm_max_kernel,
                         cudaFuncAttributeMaxDynamicSharedMemorySize, SMEM_TOTAL);
    gemm_max_kernel<<<dim3(3 * NCT, BB / TM), 256, SMEM_TOTAL>>>(labels);

    finalize_reduce_kernel<<<1, 1024>>>((float*)d_out);
}

// round 9
// speedup vs baseline: 6.1689x; 1.0509x over previous
#include <cuda_runtime.h>
#include <cuda_fp16.h>
#include <cstdint>
#include <math.h>

// ---------------------------------------------------------------------------
// MultiViewTripletLoss: dist(x,y)=sqrt(2-2 x.y) for unit vectors; hard-negative
// mining == masked row-max of dot products.  Single fp16 GEMM (K=256),
// mma.sync.m16n8k16, 128x128 tiles, 2 CTAs/SM, flip-encoded atomicMax partial
// maxima.  A.A^T symmetry: only upper-triangular tiles computed; off-diagonal
// tiles also scatter masked COLUMN maxima (atomicMax), saving 16% of GEMM work.
// (Re-bench of R7 — previous round died to container infra, kernel never ran.)
// ---------------------------------------------------------------------------

#define BB    4096
#define DD    256
#define TM    128
#define TN    128
#define NSTG  8            // K stages (256/32)
#define PITCH 80           // smem row pitch bytes (64 data + 16 pad)
#define NTRI  528          // upper-tri tiles for matrix 0 (32*33/2)
#define NBLK  (NTRI + 2 * 1024)

__device__ __align__(16) __half g_X[(size_t)3 * BB * DD];   // [m][row][k]
__device__ unsigned int g_negbits[3 * BB];   // flip-encoded row maxima
__device__ float g_pos[2 * BB];              // positive-pair dots

// smem: labc[128] @0 | labr[128] @512 | stages @1024 (3 x 20480)
#define SM_LABC 0
#define SM_LABR 512
#define SM_STG  1024
#define STG_SZ  20480
#define SM_A(b) (SM_STG + (b) * STG_SZ)
#define SM_B(b) (SM_A(b) + TM * PITCH)
#define SMEM_TOTAL (SM_STG + 3 * STG_SZ)

__device__ __forceinline__ uint32_t smem_u32(const void* p) {
    uint32_t a;
    asm("{ .reg .u64 t; cvta.to.shared.u64 t, %1; cvt.u32.u64 %0, t; }"
        : "=r"(a) : "l"(p));
    return a;
}
#define CP16(dst, src) \
    asm volatile("cp.async.cg.shared.global [%0], [%1], 16;" :: "r"(dst), "l"(src))
#define CP_COMMIT() asm volatile("cp.async.commit_group;" ::: "memory")
#define CP_WAIT(n)  asm volatile("cp.async.wait_group %0;" :: "n"(n) : "memory")
#define LDM4(r, a) \
    asm volatile("ldmatrix.sync.aligned.m8n8.x4.shared.b16 {%0,%1,%2,%3}, [%4];" \
        : "=r"((r)[0]), "=r"((r)[1]), "=r"((r)[2]), "=r"((r)[3]) : "r"(a))
#define MMA(d, a, b0, b1) \
    asm volatile("mma.sync.aligned.m16n8k16.row.col.f32.f16.f16.f32 " \
        "{%0,%1,%2,%3}, {%4,%5,%6,%7}, {%8,%9}, {%0,%1,%2,%3};" \
        : "+f"((d)[0]), "+f"((d)[1]), "+f"((d)[2]), "+f"((d)[3]) \
        : "r"((a)[0]), "r"((a)[1]), "r"((a)[2]), "r"((a)[3]), "r"(b0), "r"(b1))

// monotone float <-> uint encoding for atomicMax over signed floats
__device__ __forceinline__ unsigned int fflip(float f) {
    unsigned int u = __float_as_uint(f);
    return u ^ (unsigned int)(((int)u >> 31) | 0x80000000);
}
__device__ __forceinline__ float funflip(unsigned int m) {
    unsigned int u = (m & 0x80000000u) ? (m ^ 0x80000000u) : ~m;
    return __uint_as_float(u);
}

// --------------------------- normalize -> fp16 (+ negbits init) ------------
__global__ void norm_kernel(const float* __restrict__ anchor,
                            const float* __restrict__ positive) {
    int warp = (blockIdx.x * blockDim.x + threadIdx.x) >> 5;
    int lane = threadIdx.x & 31;
    if (warp >= 3 * BB) return;
    if (lane == 0) g_negbits[warp] = 0u;     // == fflip(very negative)

    const float* src;
    __half2* dst;
    if (warp < BB) {
        src = anchor + (size_t)warp * DD;
        dst = (__half2*)(g_X + (size_t)warp * DD);
    } else {
        int r = warp - BB, i = r >> 1, v = r & 1;   // r = i*2 + v
        src = positive + (size_t)r * DD;
        dst = (__half2*)(g_X + (size_t)((1 + v) * BB + i) * DD);
    }

    const float4* s4 = (const float4*)src;
    float4 x0 = s4[lane], x1 = s4[lane + 32];
    float ss = x0.x*x0.x + x0.y*x0.y + x0.z*x0.z + x0.w*x0.w
             + x1.x*x1.x + x1.y*x1.y + x1.z*x1.z + x1.w*x1.w;
    #pragma unroll
    for (int o = 16; o >= 1; o >>= 1) ss += __shfl_xor_sync(0xffffffffu, ss, o);
    float inv = rsqrtf(fmaxf(ss, 1e-24f));

    dst[2*lane]      = __floats2half2_rn(x0.x*inv, x0.y*inv);
    dst[2*lane + 1]  = __floats2half2_rn(x0.z*inv, x0.w*inv);
    dst[64 + 2*lane] = __floats2half2_rn(x1.x*inv, x1.y*inv);
    dst[65 + 2*lane] = __floats2half2_rn(x1.z*inv, x1.w*inv);
}

// --------------------------- GEMM + masked max (row & col) -----------------
__device__ __forceinline__ void load_stage(uint32_t sb, int buf, int s,
                                           int rowbase, int brow, int tid) {
    const char* Xg = (const char*)g_X;
    #pragma unroll
    for (int lp = 0; lp < 2; lp++) {                 // A: 512 chunks of 16B
        int idx = tid + (lp << 8);
        int row = idx >> 2, ch = idx & 3;
        uint32_t dst = sb + SM_A(buf) + row * PITCH + ch * 16;
        const char* src = Xg + (size_t)(rowbase + row) * (DD * 2) + s * 64 + ch * 16;
        CP16(dst, src);
    }
    #pragma unroll
    for (int lp = 0; lp < 2; lp++) {                 // B: 512 chunks of 16B
        int idx = tid + (lp << 8);
        int row = idx >> 2, ch = idx & 3;
        uint32_t dst = sb + SM_B(buf) + row * PITCH + ch * 16;
        const char* src = Xg + (size_t)(brow + row) * (DD * 2) + s * 64 + ch * 16;
        CP16(dst, src);
    }
    CP_COMMIT();
}

__global__ __launch_bounds__(256, 2)
void gemm_max_kernel(const int* __restrict__ labels) {
    extern __shared__ char smem[];
    uint32_t sb = smem_u32(smem);
    int* labc = (int*)(smem + SM_LABC);
    int* labr = (int*)(smem + SM_LABR);

    const int tid = threadIdx.x;
    const int lane = tid & 31;
    const int wid = tid >> 5;
    const int wm = wid >> 2, wn = wid & 3;           // 2 x 4 warp grid

    // ---- decode (m, rt, ct) from linear block id (closed form) ----
    int bid = blockIdx.x;
    int m, rt, ct;
    if (bid < NTRI) {
        m = 0;
        // row r of upper triangle: first index off(r) = r*(65-r)/2
        float bf = (float)bid;
        int r = (int)floorf(32.5f - sqrtf(32.5f * 32.5f - 2.0f * bf));
        int off = (r * (65 - r)) >> 1;
        if (off > bid)          { r--; off = (r * (65 - r)) >> 1; }
        else if (off + (32 - r) <= bid) { r++; off = (r * (65 - r)) >> 1; }
        rt = r;
        ct = r + (bid - off);
    } else {
        int t = bid - NTRI;
        m = 1 + (t >> 10);
        rt = (t & 1023) >> 5;
        ct = t & 31;
    }
    const int rowbase = rt << 7;
    const int cibase  = ct << 7;                     // col base within matrix
    const int brow    = m * BB + cibase;             // B rows in g_X

    if (tid < 128) {
        labc[tid] = labels[cibase + tid];
        labr[tid] = labels[rowbase + tid];
    }

    float acc[4][4][4];                              // [mi][ni][frag]
    #pragma unroll
    for (int i = 0; i < 4; i++)
        #pragma unroll
        for (int j = 0; j < 4; j++)
            #pragma unroll
            for (int k = 0; k < 4; k++) acc[i][j][k] = 0.f;

    load_stage(sb, 0, 0, rowbase, brow, tid);
    load_stage(sb, 1, 1, rowbase, brow, tid);

    // warp tile 64x32: A rows wm*64 + mi*16, B cols wn*32 + ni2*16
    const uint32_t a_off = (wm * 64 + (lane & 15)) * PITCH + ((lane >> 4) & 1) * 16;
    const uint32_t b_off = (wn * 32 + (lane & 7) + ((lane >> 4) & 1) * 8) * PITCH
                         + ((lane >> 3) & 1) * 16;

    for (int s = 0; s < NSTG; s++) {
        int buf = s % 3;
        CP_WAIT(1);
        __syncthreads();

        uint32_t ab = sb + SM_A(buf) + a_off;
        uint32_t bb = sb + SM_B(buf) + b_off;
        #pragma unroll
        for (int ks = 0; ks < 2; ks++) {
            uint32_t af[4][4];
            #pragma unroll
            for (int mi = 0; mi < 4; mi++)
                LDM4(af[mi], ab + ks * 32 + mi * 16 * PITCH);
            #pragma unroll
            for (int ni2 = 0; ni2 < 2; ni2++) {
                uint32_t bf[4];
                LDM4(bf, bb + ks * 32 + ni2 * 16 * PITCH);
                #pragma unroll
                for (int mi = 0; mi < 4; mi++) {
                    MMA(acc[mi][2*ni2],   af[mi], bf[0], bf[1]);
                    MMA(acc[mi][2*ni2+1], af[mi], bf[2], bf[3]);
                }
            }
        }
        __syncthreads();
        if (s + 2 < NSTG)
            load_stage(sb, (s + 2) % 3, s + 2, rowbase, brow, tid);
    }

    // ------- epilogue 1: per-row masked max (+ diagonal positives) ---------
    #pragma unroll
    for (int mi = 0; mi < 4; mi++) {
        #pragma unroll
        for (int hi = 0; hi < 2; hi++) {
            int lr = wm * 64 + mi * 16 + hi * 8 + (lane >> 2);
            int rlab = labr[lr];
            int grow = rowbase + lr;
            float mx = -1e30f, pv = 0.f;
            int match = 0;
            #pragma unroll
            for (int ni = 0; ni < 4; ni++) {
                int c = wn * 32 + ni * 8 + 2 * (lane & 3);
                float v0 = acc[mi][ni][hi * 2 + 0];
                float v1 = acc[mi][ni][hi * 2 + 1];
                if (labc[c]     != rlab) mx = fmaxf(mx, v0);
                if (labc[c + 1] != rlab) mx = fmaxf(mx, v1);
                if (m > 0) {
                    if (cibase + c == grow)     { pv += v0; match = 1; }
                    if (cibase + c + 1 == grow) { pv += v1; match = 1; }
                }
            }
            mx = fmaxf(mx, __shfl_xor_sync(0xffffffffu, mx, 1));
            mx = fmaxf(mx, __shfl_xor_sync(0xffffffffu, mx, 2));
            pv += __shfl_xor_sync(0xffffffffu, pv, 1);
            pv += __shfl_xor_sync(0xffffffffu, pv, 2);
            match |= __shfl_xor_sync(0xffffffffu, match, 1);
            match |= __shfl_xor_sync(0xffffffffu, match, 2);
            if ((lane & 3) == 0) {
                atomicMax(&g_negbits[m * BB + grow], fflip(mx));
                if (m > 0 && match) g_pos[(m - 1) * BB + grow] = pv;
            }
        }
    }

    // ------- epilogue 2 (m=0 off-diagonal): per-column masked max ----------
    if (m == 0 && rt != ct) {
        #pragma unroll
        for (int ni = 0; ni < 4; ni++) {
            int c = wn * 32 + ni * 8 + 2 * (lane & 3);
            int cl0 = labc[c], cl1 = labc[c + 1];
            float cm0 = -1e30f, cm1 = -1e30f;
            #pragma unroll
            for (int mi = 0; mi < 4; mi++) {
                #pragma unroll
                for (int hi = 0; hi < 2; hi++) {
                    int lr = wm * 64 + mi * 16 + hi * 8 + (lane >> 2);
                    int rl = labr[lr];
                    float v0 = acc[mi][ni][hi * 2 + 0];
                    float v1 = acc[mi][ni][hi * 2 + 1];
                    if (rl != cl0) cm0 = fmaxf(cm0, v0);
                    if (rl != cl1) cm1 = fmaxf(cm1, v1);
                }
            }
            #pragma unroll
            for (int o = 4; o <= 16; o <<= 1) {
                cm0 = fmaxf(cm0, __shfl_xor_sync(0xffffffffu, cm0, o));
                cm1 = fmaxf(cm1, __shfl_xor_sync(0xffffffffu, cm1, o));
            }
            if (lane < 4) {
                atomicMax(&g_negbits[cibase + c],     fflip(cm0));
                atomicMax(&g_negbits[cibase + c + 1], fflip(cm1));
            }
        }
    }
}

// ------------------- fused finalize + deterministic reduce -----------------
__global__ __launch_bounds__(1024, 1)
void finalize_reduce_kernel(float* __restrict__ out) {
    __shared__ float s[1024];
    float tot = 0.f;
    #pragma unroll
    for (int r = 0; r < 4; r++) {
        int i = threadIdx.x + (r << 10);
        float ma = funflip(g_negbits[i]);
        float m0 = funflip(g_negbits[BB + i]);
        float m1 = funflip(g_negbits[2 * BB + i]);
        float d0 = g_pos[i], d1 = g_pos[BB + i];
        float neg0 = sqrtf(fmaxf(2.f - 2.f * fmaxf(ma, m0), 1e-12f));
        float neg1 = sqrtf(fmaxf(2.f - 2.f * fmaxf(ma, m1), 1e-12f));
        float pos0 = sqrtf(fmaxf(2.f - 2.f * d0, 1e-12f));
        float pos1 = sqrtf(fmaxf(2.f - 2.f * d1, 1e-12f));
        tot += fmaxf(pos0 - neg0 + 1.0f, 0.0f) + fmaxf(pos1 - neg1 + 1.0f, 0.0f);
    }
    s[threadIdx.x] = tot;
    __syncthreads();
    #pragma unroll
    for (int o = 512; o >= 1; o >>= 1) {
        if (threadIdx.x < o) s[threadIdx.x] += s[threadIdx.x + o];
        __syncthreads();
    }
    if (threadIdx.x == 0) out[0] = s[0] * (1.0f / (2.0f * BB));
}

// ---------------------------------------------------------------------------
extern "C" void kernel_launch(void* const* d_in, const int* in_sizes, int n_in,
                              void* d_out, int out_size) {
    const float* anchor = nullptr;
    const float* positive = nullptr;
    const int*   labels = nullptr;
    for (int i = 0; i < n_in; i++) {
        if (in_sizes[i] == BB * DD)          anchor   = (const float*)d_in[i];
        else if (in_sizes[i] == 2 * BB * DD) positive = (const float*)d_in[i];
        else if (in_sizes[i] == BB)          labels   = (const int*)d_in[i];
    }

    norm_kernel<<<1536, 256>>>(anchor, positive);

    cudaFuncSetAttribute(gemm_max_kernel,
                         cudaFuncAttributeMaxDynamicSharedMemorySize, SMEM_TOTAL);
    gemm_max_kernel<<<NBLK, 256, SMEM_TOTAL>>>(labels);

    finalize_reduce_kernel<<<1, 1024>>>((float*)d_out);
}